// round 3
// baseline (speedup 1.0000x reference)
#include <cuda_runtime.h>
#include <math.h>

#define PERI_BLOCKS 592      // 4 blocks/SM * 148 SMs
#define PERI_THREADS 256

__device__ double g_peri;
__device__ float  g_r, g_gtr, g_gtperi;
__device__ int    g_detect;   // >0 => A is byte-layout (bool); ==0 => int32 layout

__device__ __forceinline__ float fsqrt_fast(float x) {
    float r;
    asm("sqrt.approx.f32 %0, %1;" : "=f"(r) : "f"(x));
    return r;
}

// ---------------------------------------------------------------------------
// Small-stats kernel: single block. Computes r, gtr, gtperi; zeroes globals.
// ---------------------------------------------------------------------------
__global__ void stats_kernel(const float2* __restrict__ verts,
                             const float2* __restrict__ gts,
                             int n, int m) {
    __shared__ float s1[1024];
    __shared__ float s2[1024];
    const int t = threadIdx.x;
    const int nt = blockDim.x;

    if (t == 0) { g_peri = 0.0; g_detect = 0; }

    // ---- verts centroid ----
    float ax = 0.f, ay = 0.f;
    for (int i = t; i < n; i += nt) { float2 v = verts[i]; ax += v.x; ay += v.y; }
    s1[t] = ax; s2[t] = ay; __syncthreads();
    for (int s = nt >> 1; s > 0; s >>= 1) {
        if (t < s) { s1[t] += s1[t + s]; s2[t] += s2[t + s]; }
        __syncthreads();
    }
    float cx = s1[0] / (float)n, cy = s2[0] / (float)n;
    __syncthreads();

    // ---- r = mean distance to centroid ----
    float rs = 0.f;
    for (int i = t; i < n; i += nt) {
        float2 v = verts[i];
        float dx = v.x - cx, dy = v.y - cy;
        rs += sqrtf(dx * dx + dy * dy);
    }
    s1[t] = rs; __syncthreads();
    for (int s = nt >> 1; s > 0; s >>= 1) {
        if (t < s) s1[t] += s1[t + s];
        __syncthreads();
    }
    if (t == 0) g_r = s1[0] / (float)n;
    __syncthreads();

    // ---- gts centroid ----
    ax = 0.f; ay = 0.f;
    for (int i = t; i < m; i += nt) { float2 v = gts[i]; ax += v.x; ay += v.y; }
    s1[t] = ax; s2[t] = ay; __syncthreads();
    for (int s = nt >> 1; s > 0; s >>= 1) {
        if (t < s) { s1[t] += s1[t + s]; s2[t] += s2[t + s]; }
        __syncthreads();
    }
    cx = s1[0] / (float)m; cy = s2[0] / (float)m;
    __syncthreads();

    // ---- gtr and gtperi ----
    float gs = 0.f, gp = 0.f;
    for (int i = t; i < m; i += nt) {
        float2 v = gts[i];
        float dx = v.x - cx, dy = v.y - cy;
        gs += sqrtf(dx * dx + dy * dy);
        float2 w = gts[(i + 1 == m) ? 0 : (i + 1)];
        float ex = v.x - w.x, ey = v.y - w.y;
        gp += sqrtf(ex * ex + ey * ey);
    }
    s1[t] = gs; s2[t] = gp; __syncthreads();
    for (int s = nt >> 1; s > 0; s >>= 1) {
        if (t < s) { s1[t] += s1[t + s]; s2[t] += s2[t + s]; }
        __syncthreads();
    }
    if (t == 0) { g_gtr = s1[0] / (float)m; g_gtperi = s2[0]; }
}

// ---------------------------------------------------------------------------
// Layout detection: in int32 layout (values 0/1, little-endian) every byte at
// offset %4 != 0 is zero. In raw bool (byte) layout ~half are nonzero.
// ---------------------------------------------------------------------------
__global__ void detect_kernel(const unsigned char* __restrict__ A) {
    int cnt = 0;
    for (int i = threadIdx.x; i < 65536; i += blockDim.x)
        if ((i & 3) != 0 && A[i] != 0) cnt++;
    for (int o = 16; o > 0; o >>= 1)
        cnt += __shfl_down_sync(0xffffffffu, cnt, o);
    if ((threadIdx.x & 31) == 0 && cnt > 0) atomicAdd(&g_detect, cnt);
}

// ---------------------------------------------------------------------------
// Pair-perimeter kernel: grid-stride over rows; verts cached in 64KB shared.
// Uniform branch selects byte-layout (uchar4) or int32-layout (int4) A reads.
// Branch-free masked accumulate: sqrt always issued, multiplied by 0/1 mask.
// ---------------------------------------------------------------------------
__global__ void peri_kernel(const float2* __restrict__ verts,
                            const void* __restrict__ Araw,
                            int n) {
    extern __shared__ float2 sv[];
    for (int i = threadIdx.x; i < n; i += blockDim.x) sv[i] = verts[i];
    __syncthreads();

    const bool bytelayout = (g_detect > 0);
    float sum0 = 0.f, sum1 = 0.f;

    for (int i = blockIdx.x; i < n; i += gridDim.x) {
        const float2 vi = sv[i];
        const int jstart  = i + 1;
        const int j4start = (jstart + 3) & ~3;
        const int npro    = j4start - jstart;

        if (bytelayout) {
            const unsigned char* __restrict__ row =
                (const unsigned char*)Araw + (size_t)i * (size_t)n;

            if ((int)threadIdx.x < npro) {
                int j = jstart + threadIdx.x;
                if (j < n && row[j]) {
                    float dx = sv[j].x - vi.x, dy = sv[j].y - vi.y;
                    sum0 += fsqrt_fast(dx * dx + dy * dy);
                }
            }
            for (int j4 = j4start + threadIdx.x * 4; j4 < n; j4 += blockDim.x * 4) {
                const uchar4 a4 = *(const uchar4*)(row + j4);
                const float2 p0 = sv[j4 + 0];
                const float2 p1 = sv[j4 + 1];
                const float2 p2 = sv[j4 + 2];
                const float2 p3 = sv[j4 + 3];
                float dx, dy;
                dx = p0.x - vi.x; dy = p0.y - vi.y;
                sum0 += fsqrt_fast(dx * dx + dy * dy) * (float)(a4.x != 0);
                dx = p1.x - vi.x; dy = p1.y - vi.y;
                sum1 += fsqrt_fast(dx * dx + dy * dy) * (float)(a4.y != 0);
                dx = p2.x - vi.x; dy = p2.y - vi.y;
                sum0 += fsqrt_fast(dx * dx + dy * dy) * (float)(a4.z != 0);
                dx = p3.x - vi.x; dy = p3.y - vi.y;
                sum1 += fsqrt_fast(dx * dx + dy * dy) * (float)(a4.w != 0);
            }
        } else {
            const int* __restrict__ row =
                (const int*)Araw + (size_t)i * (size_t)n;

            if ((int)threadIdx.x < npro) {
                int j = jstart + threadIdx.x;
                if (j < n && row[j]) {
                    float dx = sv[j].x - vi.x, dy = sv[j].y - vi.y;
                    sum0 += fsqrt_fast(dx * dx + dy * dy);
                }
            }
            for (int j4 = j4start + threadIdx.x * 4; j4 < n; j4 += blockDim.x * 4) {
                const int4 a4 = *(const int4*)(row + j4);
                const float2 p0 = sv[j4 + 0];
                const float2 p1 = sv[j4 + 1];
                const float2 p2 = sv[j4 + 2];
                const float2 p3 = sv[j4 + 3];
                float dx, dy;
                dx = p0.x - vi.x; dy = p0.y - vi.y;
                sum0 += fsqrt_fast(dx * dx + dy * dy) * (float)(a4.x != 0);
                dx = p1.x - vi.x; dy = p1.y - vi.y;
                sum1 += fsqrt_fast(dx * dx + dy * dy) * (float)(a4.y != 0);
                dx = p2.x - vi.x; dy = p2.y - vi.y;
                sum0 += fsqrt_fast(dx * dx + dy * dy) * (float)(a4.z != 0);
                dx = p3.x - vi.x; dy = p3.y - vi.y;
                sum1 += fsqrt_fast(dx * dx + dy * dy) * (float)(a4.w != 0);
            }
        }
    }

    float sum = sum0 + sum1;
    // warp reduce
    for (int o = 16; o > 0; o >>= 1)
        sum += __shfl_down_sync(0xffffffffu, sum, o);

    __shared__ float wsum[PERI_THREADS / 32];
    if ((threadIdx.x & 31) == 0) wsum[threadIdx.x >> 5] = sum;
    __syncthreads();

    if (threadIdx.x < (PERI_THREADS / 32)) {
        float b = wsum[threadIdx.x];
        for (int o = (PERI_THREADS / 64); o > 0; o >>= 1)
            b += __shfl_down_sync(0xffu, b, o);
        if (threadIdx.x == 0) atomicAdd(&g_peri, (double)b);
    }
}

// ---------------------------------------------------------------------------
// Finalize: combine terms, write scalar output.
// ---------------------------------------------------------------------------
__global__ void final_kernel(float* out) {
    float peri = (float)g_peri;
    float d1 = g_r - g_gtr;
    float d2 = peri - g_gtperi;
    out[0] = d1 * d1 + d2 * d2;
}

extern "C" void kernel_launch(void* const* d_in, const int* in_sizes, int n_in,
                              void* d_out, int out_size) {
    const float2* verts = (const float2*)d_in[0];
    const float2* gts   = (const float2*)d_in[1];
    const void*   A     = d_in[2];
    float* out = (float*)d_out;

    const int n = in_sizes[0] / 2;   // 8192
    const int m = in_sizes[1] / 2;   // 8192

    const size_t smem = (size_t)n * sizeof(float2);   // 64 KB
    cudaFuncSetAttribute(peri_kernel,
                         cudaFuncAttributeMaxDynamicSharedMemorySize,
                         (int)smem + 1024);

    stats_kernel<<<1, 1024>>>(verts, gts, n, m);
    detect_kernel<<<1, 256>>>((const unsigned char*)A);
    peri_kernel<<<PERI_BLOCKS, PERI_THREADS, smem>>>(verts, A, n);
    final_kernel<<<1, 1>>>(out);
}

// round 4
// speedup vs baseline: 1.1834x; 1.1834x over previous
#include <cuda_runtime.h>
#include <math.h>

#define PERI_BLOCKS 444      // 3 blocks/SM * 148 SMs (64KB smem => 3 resident)
#define PERI_THREADS 256

__device__ double g_peri;
__device__ float  g_r, g_gtr, g_gtperi;
__device__ int    g_detect;   // >0 => A is byte-layout (bool); ==0 => int32 layout

__device__ __forceinline__ float fsqrt_fast(float x) {
    float r;
    asm("sqrt.approx.f32 %0, %1;" : "=f"(r) : "f"(x));
    return r;
}

// ---------------------------------------------------------------------------
// Stats + layout-detect kernel: single block of 1024 threads.
// Computes r, gtr, gtperi; zeroes g_peri; detects A layout.
// ---------------------------------------------------------------------------
__global__ void stats_kernel(const float2* __restrict__ verts,
                             const float2* __restrict__ gts,
                             const unsigned char* __restrict__ A,
                             int n, int m) {
    __shared__ float s1[1024];
    __shared__ float s2[1024];
    const int t = threadIdx.x;
    const int nt = blockDim.x;

    if (t == 0) { g_peri = 0.0; g_detect = 0; }
    __syncthreads();

    // ---- layout detect: int32 {0,1} layout has zero bytes at offsets %4!=0 ----
    int cnt = 0;
    for (int i = t; i < 65536; i += nt)
        if ((i & 3) != 0 && A[i] != 0) cnt++;
    for (int o = 16; o > 0; o >>= 1)
        cnt += __shfl_down_sync(0xffffffffu, cnt, o);
    if ((t & 31) == 0 && cnt > 0) atomicAdd(&g_detect, cnt);

    // ---- verts centroid ----
    float ax = 0.f, ay = 0.f;
    for (int i = t; i < n; i += nt) { float2 v = verts[i]; ax += v.x; ay += v.y; }
    s1[t] = ax; s2[t] = ay; __syncthreads();
    for (int s = nt >> 1; s > 0; s >>= 1) {
        if (t < s) { s1[t] += s1[t + s]; s2[t] += s2[t + s]; }
        __syncthreads();
    }
    float cx = s1[0] / (float)n, cy = s2[0] / (float)n;
    __syncthreads();

    // ---- r = mean distance to centroid ----
    float rs = 0.f;
    for (int i = t; i < n; i += nt) {
        float2 v = verts[i];
        float dx = v.x - cx, dy = v.y - cy;
        rs += sqrtf(dx * dx + dy * dy);
    }
    s1[t] = rs; __syncthreads();
    for (int s = nt >> 1; s > 0; s >>= 1) {
        if (t < s) s1[t] += s1[t + s];
        __syncthreads();
    }
    if (t == 0) g_r = s1[0] / (float)n;
    __syncthreads();

    // ---- gts centroid ----
    ax = 0.f; ay = 0.f;
    for (int i = t; i < m; i += nt) { float2 v = gts[i]; ax += v.x; ay += v.y; }
    s1[t] = ax; s2[t] = ay; __syncthreads();
    for (int s = nt >> 1; s > 0; s >>= 1) {
        if (t < s) { s1[t] += s1[t + s]; s2[t] += s2[t + s]; }
        __syncthreads();
    }
    cx = s1[0] / (float)m; cy = s2[0] / (float)m;
    __syncthreads();

    // ---- gtr and gtperi ----
    float gs = 0.f, gp = 0.f;
    for (int i = t; i < m; i += nt) {
        float2 v = gts[i];
        float dx = v.x - cx, dy = v.y - cy;
        gs += sqrtf(dx * dx + dy * dy);
        float2 w = gts[(i + 1 == m) ? 0 : (i + 1)];
        float ex = v.x - w.x, ey = v.y - w.y;
        gp += sqrtf(ex * ex + ey * ey);
    }
    s1[t] = gs; s2[t] = gp; __syncthreads();
    for (int s = nt >> 1; s > 0; s >>= 1) {
        if (t < s) { s1[t] += s1[t + s]; s2[t] += s2[t + s]; }
        __syncthreads();
    }
    if (t == 0) { g_gtr = s1[0] / (float)m; g_gtperi = s2[0]; }
}

// ---------------------------------------------------------------------------
// Pair-perimeter kernel. Grid-stride over rows; verts in 64KB shared.
// CONSECUTIVE-THREAD column mapping: j = i+1+tid, stride blockDim =>
// conflict-free LDS.64 (consecutive float2 per warp) and coalesced A reads.
// ---------------------------------------------------------------------------
__global__ void __launch_bounds__(PERI_THREADS)
peri_kernel(const float2* __restrict__ verts,
            const void* __restrict__ Araw,
            int n) {
    extern __shared__ float2 sv[];
    for (int i = threadIdx.x; i < n; i += blockDim.x) sv[i] = verts[i];
    __syncthreads();

    const bool bytelayout = (g_detect > 0);
    float sum0 = 0.f, sum1 = 0.f;

    for (int i = blockIdx.x; i < n; i += gridDim.x) {
        const float2 vi = sv[i];
        const int jstart = i + 1 + threadIdx.x;

        if (bytelayout) {
            const unsigned char* __restrict__ row =
                (const unsigned char*)Araw + (size_t)i * (size_t)n;
            int j = jstart;
            #pragma unroll 4
            for (; j + (int)blockDim.x < n; j += 2 * blockDim.x) {
                unsigned int a0 = row[j];
                unsigned int a1 = row[j + blockDim.x];
                float2 p0 = sv[j];
                float2 p1 = sv[j + blockDim.x];
                float dx0 = p0.x - vi.x, dy0 = p0.y - vi.y;
                float dx1 = p1.x - vi.x, dy1 = p1.y - vi.y;
                float s0 = fsqrt_fast(dx0 * dx0 + dy0 * dy0);
                float s1v = fsqrt_fast(dx1 * dx1 + dy1 * dy1);
                sum0 += a0 ? s0 : 0.0f;
                sum1 += a1 ? s1v : 0.0f;
            }
            if (j < n) {
                unsigned int a0 = row[j];
                float2 p0 = sv[j];
                float dx0 = p0.x - vi.x, dy0 = p0.y - vi.y;
                float s0 = fsqrt_fast(dx0 * dx0 + dy0 * dy0);
                sum0 += a0 ? s0 : 0.0f;
            }
        } else {
            const int* __restrict__ row =
                (const int*)Araw + (size_t)i * (size_t)n;
            int j = jstart;
            #pragma unroll 4
            for (; j + (int)blockDim.x < n; j += 2 * blockDim.x) {
                int a0 = row[j];
                int a1 = row[j + blockDim.x];
                float2 p0 = sv[j];
                float2 p1 = sv[j + blockDim.x];
                float dx0 = p0.x - vi.x, dy0 = p0.y - vi.y;
                float dx1 = p1.x - vi.x, dy1 = p1.y - vi.y;
                float s0 = fsqrt_fast(dx0 * dx0 + dy0 * dy0);
                float s1v = fsqrt_fast(dx1 * dx1 + dy1 * dy1);
                sum0 += a0 ? s0 : 0.0f;
                sum1 += a1 ? s1v : 0.0f;
            }
            if (j < n) {
                int a0 = row[j];
                float2 p0 = sv[j];
                float dx0 = p0.x - vi.x, dy0 = p0.y - vi.y;
                float s0 = fsqrt_fast(dx0 * dx0 + dy0 * dy0);
                sum0 += a0 ? s0 : 0.0f;
            }
        }
    }

    float sum = sum0 + sum1;
    for (int o = 16; o > 0; o >>= 1)
        sum += __shfl_down_sync(0xffffffffu, sum, o);

    __shared__ float wsum[PERI_THREADS / 32];
    if ((threadIdx.x & 31) == 0) wsum[threadIdx.x >> 5] = sum;
    __syncthreads();

    if (threadIdx.x < (PERI_THREADS / 32)) {
        float b = wsum[threadIdx.x];
        for (int o = (PERI_THREADS / 64); o > 0; o >>= 1)
            b += __shfl_down_sync(0xffu, b, o);
        if (threadIdx.x == 0) atomicAdd(&g_peri, (double)b);
    }
}

// ---------------------------------------------------------------------------
// Finalize: combine terms, write scalar output.
// ---------------------------------------------------------------------------
__global__ void final_kernel(float* out) {
    float peri = (float)g_peri;
    float d1 = g_r - g_gtr;
    float d2 = peri - g_gtperi;
    out[0] = d1 * d1 + d2 * d2;
}

extern "C" void kernel_launch(void* const* d_in, const int* in_sizes, int n_in,
                              void* d_out, int out_size) {
    const float2* verts = (const float2*)d_in[0];
    const float2* gts   = (const float2*)d_in[1];
    const void*   A     = d_in[2];
    float* out = (float*)d_out;

    const int n = in_sizes[0] / 2;   // 8192
    const int m = in_sizes[1] / 2;   // 8192

    const size_t smem = (size_t)n * sizeof(float2);   // 64 KB
    cudaFuncSetAttribute(peri_kernel,
                         cudaFuncAttributeMaxDynamicSharedMemorySize,
                         (int)smem + 1024);

    stats_kernel<<<1, 1024>>>(verts, gts, (const unsigned char*)A, n, m);
    peri_kernel<<<PERI_BLOCKS, PERI_THREADS, smem>>>(verts, A, n);
    final_kernel<<<1, 1>>>(out);
}

// round 5
// speedup vs baseline: 1.6596x; 1.4025x over previous
#include <cuda_runtime.h>
#include <math.h>

#define PERI_BLOCKS 444      // 3 blocks/SM * 148 SMs (64KB smem => 3 resident)
#define PERI_THREADS 256
#define UNROLL 8

__device__ double g_peri;

__device__ __forceinline__ float fsqrt_fast(float x) {
    float r;
    asm("sqrt.approx.f32 %0, %1;" : "=f"(r) : "f"(x));
    return r;
}

// ---------------------------------------------------------------------------
// Pair-perimeter kernel. Launched FIRST (no prologue dependency).
// - verts cached in 64KB shared, consecutive-thread column mapping (conflict-
//   free LDS.64, coalesced A loads).
// - 8-deep explicit load batch => MLP 8 per warp to cover DRAM latency.
// - per-block self-detection of A layout (int32 vs bool bytes) from a fixed
//   4KB window: int32 {0,1} layout has zero bytes at offsets %4 != 0.
// ---------------------------------------------------------------------------
__global__ void __launch_bounds__(PERI_THREADS)
peri_kernel(const float2* __restrict__ verts,
            const void* __restrict__ Araw,
            int n) {
    extern __shared__ float2 sv[];
    __shared__ int s_bytelayout;

    if (threadIdx.x == 0) s_bytelayout = 0;
    for (int i = threadIdx.x; i < n; i += blockDim.x) sv[i] = verts[i];

    {   // layout detect over first 4KB (identical result in every block)
        const unsigned char* __restrict__ Ab = (const unsigned char*)Araw;
        int hit = 0;
        for (int k = threadIdx.x; k < 4096; k += blockDim.x)
            if ((k & 3) != 0 && Ab[k] != 0) hit = 1;
        if (hit) s_bytelayout = 1;   // benign race: all writers store 1
    }
    __syncthreads();

    const bool bytelayout = (s_bytelayout != 0);
    const int B = blockDim.x;
    float sum0 = 0.f, sum1 = 0.f;

    for (int i = blockIdx.x; i < n; i += gridDim.x) {
        const float2 vi = sv[i];

        if (bytelayout) {
            const unsigned char* __restrict__ row =
                (const unsigned char*)Araw + (size_t)i * (size_t)n;
            for (int j = i + 1 + threadIdx.x; j < n; j += UNROLL * B) {
                unsigned int a[UNROLL];
                float2 p[UNROLL];
                #pragma unroll
                for (int u = 0; u < UNROLL; u++) {
                    int jj = j + u * B;
                    a[u] = (jj < n) ? (unsigned int)row[jj] : 0u;
                }
                #pragma unroll
                for (int u = 0; u < UNROLL; u++) {
                    int jj = j + u * B;
                    p[u] = sv[(jj < n) ? jj : 0];
                }
                #pragma unroll
                for (int u = 0; u < UNROLL; u++) {
                    float dx = p[u].x - vi.x, dy = p[u].y - vi.y;
                    float s = fsqrt_fast(dx * dx + dy * dy);
                    if (u & 1) sum1 += a[u] ? s : 0.0f;
                    else       sum0 += a[u] ? s : 0.0f;
                }
            }
        } else {
            const int* __restrict__ row =
                (const int*)Araw + (size_t)i * (size_t)n;
            for (int j = i + 1 + threadIdx.x; j < n; j += UNROLL * B) {
                int a[UNROLL];
                float2 p[UNROLL];
                #pragma unroll
                for (int u = 0; u < UNROLL; u++) {
                    int jj = j + u * B;
                    a[u] = (jj < n) ? row[jj] : 0;
                }
                #pragma unroll
                for (int u = 0; u < UNROLL; u++) {
                    int jj = j + u * B;
                    p[u] = sv[(jj < n) ? jj : 0];
                }
                #pragma unroll
                for (int u = 0; u < UNROLL; u++) {
                    float dx = p[u].x - vi.x, dy = p[u].y - vi.y;
                    float s = fsqrt_fast(dx * dx + dy * dy);
                    if (u & 1) sum1 += a[u] ? s : 0.0f;
                    else       sum0 += a[u] ? s : 0.0f;
                }
            }
        }
    }

    float sum = sum0 + sum1;
    for (int o = 16; o > 0; o >>= 1)
        sum += __shfl_down_sync(0xffffffffu, sum, o);

    __shared__ float wsum[PERI_THREADS / 32];
    if ((threadIdx.x & 31) == 0) wsum[threadIdx.x >> 5] = sum;
    __syncthreads();

    if (threadIdx.x < (PERI_THREADS / 32)) {
        float b = wsum[threadIdx.x];
        for (int o = (PERI_THREADS / 64); o > 0; o >>= 1)
            b += __shfl_down_sync(0xffu, b, o);
        if (threadIdx.x == 0) atomicAdd(&g_peri, (double)b);
    }
}

// ---------------------------------------------------------------------------
// Fused stats + finalize: single block, 1024 threads, shfl-first reductions.
// Computes r, gtr, gtperi, combines with g_peri, writes scalar output.
// ---------------------------------------------------------------------------
__device__ __forceinline__ float block_sum(float v, float* sh) {
    const int t = threadIdx.x;
    for (int o = 16; o > 0; o >>= 1)
        v += __shfl_down_sync(0xffffffffu, v, o);
    if ((t & 31) == 0) sh[t >> 5] = v;
    __syncthreads();
    float r = 0.f;
    if (t < 32) {
        r = (t < (int)(blockDim.x >> 5)) ? sh[t] : 0.f;
        for (int o = 16; o > 0; o >>= 1)
            r += __shfl_down_sync(0xffffffffu, r, o);
        if (t == 0) sh[0] = r;
    }
    __syncthreads();
    r = sh[0];
    __syncthreads();
    return r;
}

__global__ void statsfinal_kernel(const float2* __restrict__ verts,
                                  const float2* __restrict__ gts,
                                  float* __restrict__ out,
                                  int n, int m) {
    __shared__ float sh[32];
    const int t = threadIdx.x;
    const int nt = blockDim.x;

    // verts centroid
    float ax = 0.f, ay = 0.f;
    for (int i = t; i < n; i += nt) { float2 v = verts[i]; ax += v.x; ay += v.y; }
    float cx = block_sum(ax, sh) / (float)n;
    float cy = block_sum(ay, sh) / (float)n;

    // r
    float rs = 0.f;
    for (int i = t; i < n; i += nt) {
        float2 v = verts[i];
        float dx = v.x - cx, dy = v.y - cy;
        rs += sqrtf(dx * dx + dy * dy);
    }
    float r = block_sum(rs, sh) / (float)n;

    // gts centroid
    float gx = 0.f, gy = 0.f;
    for (int i = t; i < m; i += nt) { float2 v = gts[i]; gx += v.x; gy += v.y; }
    float gcx = block_sum(gx, sh) / (float)m;
    float gcy = block_sum(gy, sh) / (float)m;

    // gtr and gtperi
    float gs = 0.f, gp = 0.f;
    for (int i = t; i < m; i += nt) {
        float2 v = gts[i];
        float dx = v.x - gcx, dy = v.y - gcy;
        gs += sqrtf(dx * dx + dy * dy);
        float2 w = gts[(i + 1 == m) ? 0 : (i + 1)];
        float ex = v.x - w.x, ey = v.y - w.y;
        gp += sqrtf(ex * ex + ey * ey);
    }
    float gtr    = block_sum(gs, sh) / (float)m;
    float gtperi = block_sum(gp, sh);

    if (t == 0) {
        float peri = (float)g_peri;
        float d1 = r - gtr;
        float d2 = peri - gtperi;
        out[0] = d1 * d1 + d2 * d2;
    }
}

extern "C" void kernel_launch(void* const* d_in, const int* in_sizes, int n_in,
                              void* d_out, int out_size) {
    const float2* verts = (const float2*)d_in[0];
    const float2* gts   = (const float2*)d_in[1];
    const void*   A     = d_in[2];
    float* out = (float*)d_out;

    const int n = in_sizes[0] / 2;   // 8192
    const int m = in_sizes[1] / 2;   // 8192

    void* peri_addr = nullptr;
    cudaGetSymbolAddress(&peri_addr, g_peri);
    cudaMemsetAsync(peri_addr, 0, sizeof(double));

    const size_t smem = (size_t)n * sizeof(float2);   // 64 KB
    cudaFuncSetAttribute(peri_kernel,
                         cudaFuncAttributeMaxDynamicSharedMemorySize,
                         (int)smem + 1024);

    peri_kernel<<<PERI_BLOCKS, PERI_THREADS, smem>>>(verts, A, n);
    statsfinal_kernel<<<1, 1024>>>(verts, gts, out, n, m);
}

// round 6
// speedup vs baseline: 1.7591x; 1.0599x over previous
#include <cuda_runtime.h>
#include <math.h>

#define PERI_BLOCKS 444      // 3 blocks/SM * 148 SMs (64KB smem => 3 resident)
#define PERI_THREADS 256
#define VB 4                 // vector batches per iteration (4 pairs each)

__device__ unsigned long long g_accum[2];   // [0] = peri (double bits), [1] = done counter
__device__ float g_r, g_gtr, g_gtperi;

__device__ __forceinline__ float fsqrt_fast(float x) {
    float r;
    asm("sqrt.approx.f32 %0, %1;" : "=f"(r) : "f"(x));
    return r;
}

// block-wide sum for 256 threads (8 warps)
__device__ __forceinline__ float block_sum256(float v, float* sh) {
    const int t = threadIdx.x;
    for (int o = 16; o > 0; o >>= 1)
        v += __shfl_down_sync(0xffffffffu, v, o);
    if ((t & 31) == 0) sh[t >> 5] = v;
    __syncthreads();
    float r = 0.f;
    if (t < 32) {
        r = (t < 8) ? sh[t] : 0.f;
        for (int o = 4; o > 0; o >>= 1)
            r += __shfl_down_sync(0xffffffffu, r, o);
        if (t == 0) sh[0] = r;
    }
    __syncthreads();
    r = sh[0];
    __syncthreads();
    return r;
}

// ---------------------------------------------------------------------------
// Single fused kernel.
//  * All blocks: grid-stride rows of the masked pair-distance sum.
//    - verts in shared as SoA (sx, sy) => conflict-free float4 LDS.128
//    - A read as int4 (int32 layout) or uchar4 (byte layout), 4 pairs/LDG,
//      VB-deep batch => 16 lines in flight per warp
//    - per-block layout self-detection from first 4KB of A
//  * Block 0 additionally computes r, gtr, gtperi before its rows.
//  * Last block to finish combines everything and writes out[0].
// ---------------------------------------------------------------------------
__global__ void __launch_bounds__(PERI_THREADS)
fused_kernel(const float2* __restrict__ verts,
             const float2* __restrict__ gts,
             const void* __restrict__ Araw,
             float* __restrict__ out,
             int n, int m) {
    extern __shared__ float smem[];
    float* sx = smem;          // n floats
    float* sy = smem + n;      // n floats
    __shared__ float sh[32];
    __shared__ int s_bytelayout;

    const int t = threadIdx.x;
    const int B = blockDim.x;

    if (t == 0) s_bytelayout = 0;
    for (int i = t; i < n; i += B) {
        float2 v = verts[i];
        sx[i] = v.x; sy[i] = v.y;
    }
    {   // layout detect: int32 {0,1} layout has zero bytes at offsets %4 != 0
        const unsigned char* __restrict__ Ab = (const unsigned char*)Araw;
        int hit = 0;
        for (int k = t; k < 4096; k += B)
            if ((k & 3) != 0 && Ab[k] != 0) hit = 1;
        if (hit) s_bytelayout = 1;
    }
    __syncthreads();

    // ---- block 0: stats (r, gtr, gtperi) ----
    if (blockIdx.x == 0) {
        float ax = 0.f, ay = 0.f;
        for (int i = t; i < n; i += B) { ax += sx[i]; ay += sy[i]; }
        float cx = block_sum256(ax, sh) / (float)n;
        float cy = block_sum256(ay, sh) / (float)n;

        float rs = 0.f;
        for (int i = t; i < n; i += B) {
            float dx = sx[i] - cx, dy = sy[i] - cy;
            rs += sqrtf(dx * dx + dy * dy);
        }
        float r = block_sum256(rs, sh) / (float)n;

        float gx = 0.f, gy = 0.f;
        for (int i = t; i < m; i += B) { float2 v = gts[i]; gx += v.x; gy += v.y; }
        float gcx = block_sum256(gx, sh) / (float)m;
        float gcy = block_sum256(gy, sh) / (float)m;

        float gs = 0.f, gp = 0.f;
        for (int i = t; i < m; i += B) {
            float2 v = gts[i];
            float dx = v.x - gcx, dy = v.y - gcy;
            gs += sqrtf(dx * dx + dy * dy);
            float2 w = gts[(i + 1 == m) ? 0 : (i + 1)];
            float ex = v.x - w.x, ey = v.y - w.y;
            gp += sqrtf(ex * ex + ey * ey);
        }
        float gtr    = block_sum256(gs, sh) / (float)m;
        float gtperi = block_sum256(gp, sh);

        if (t == 0) { g_r = r; g_gtr = gtr; g_gtperi = gtperi; }
    }

    // ---- pair-perimeter rows ----
    const bool bytelayout = (s_bytelayout != 0);
    float sum0 = 0.f, sum1 = 0.f;

    for (int i = blockIdx.x; i < n; i += gridDim.x) {
        const float vix = sx[i], viy = sy[i];
        const int jstart  = i + 1;
        const int j4start = (jstart + 3) & ~3;
        const int npro    = j4start - jstart;

        // unaligned head (0..3 elements)
        if (t < npro) {
            int j = jstart + t;
            if (j < n) {
                unsigned int a;
                if (bytelayout) a = ((const unsigned char*)Araw)[(size_t)i * n + j];
                else            a = (unsigned int)((const int*)Araw)[(size_t)i * n + j];
                float dx = sx[j] - vix, dy = sy[j] - viy;
                float s = fsqrt_fast(dx * dx + dy * dy);
                sum0 += a ? s : 0.0f;
            }
        }

        if (bytelayout) {
            const unsigned char* __restrict__ row =
                (const unsigned char*)Araw + (size_t)i * (size_t)n;
            for (int jb = j4start + 4 * t; jb < n; jb += VB * 4 * B) {
                uchar4 a[VB]; float4 px[VB]; float4 py[VB];
                #pragma unroll
                for (int u = 0; u < VB; u++) {
                    int j4 = jb + u * 4 * B;
                    a[u] = (j4 < n) ? *(const uchar4*)(row + j4)
                                    : make_uchar4(0, 0, 0, 0);
                }
                #pragma unroll
                for (int u = 0; u < VB; u++) {
                    int j4 = jb + u * 4 * B;
                    int js = (j4 < n) ? j4 : 0;
                    px[u] = *(const float4*)(sx + js);
                    py[u] = *(const float4*)(sy + js);
                }
                #pragma unroll
                for (int u = 0; u < VB; u++) {
                    float dx, dy, s;
                    dx = px[u].x - vix; dy = py[u].x - viy;
                    s = fsqrt_fast(dx * dx + dy * dy); sum0 += a[u].x ? s : 0.0f;
                    dx = px[u].y - vix; dy = py[u].y - viy;
                    s = fsqrt_fast(dx * dx + dy * dy); sum1 += a[u].y ? s : 0.0f;
                    dx = px[u].z - vix; dy = py[u].z - viy;
                    s = fsqrt_fast(dx * dx + dy * dy); sum0 += a[u].z ? s : 0.0f;
                    dx = px[u].w - vix; dy = py[u].w - viy;
                    s = fsqrt_fast(dx * dx + dy * dy); sum1 += a[u].w ? s : 0.0f;
                }
            }
        } else {
            const int* __restrict__ row =
                (const int*)Araw + (size_t)i * (size_t)n;
            for (int jb = j4start + 4 * t; jb < n; jb += VB * 4 * B) {
                int4 a[VB]; float4 px[VB]; float4 py[VB];
                #pragma unroll
                for (int u = 0; u < VB; u++) {
                    int j4 = jb + u * 4 * B;
                    a[u] = (j4 < n) ? *(const int4*)(row + j4)
                                    : make_int4(0, 0, 0, 0);
                }
                #pragma unroll
                for (int u = 0; u < VB; u++) {
                    int j4 = jb + u * 4 * B;
                    int js = (j4 < n) ? j4 : 0;
                    px[u] = *(const float4*)(sx + js);
                    py[u] = *(const float4*)(sy + js);
                }
                #pragma unroll
                for (int u = 0; u < VB; u++) {
                    float dx, dy, s;
                    dx = px[u].x - vix; dy = py[u].x - viy;
                    s = fsqrt_fast(dx * dx + dy * dy); sum0 += a[u].x ? s : 0.0f;
                    dx = px[u].y - vix; dy = py[u].y - viy;
                    s = fsqrt_fast(dx * dx + dy * dy); sum1 += a[u].y ? s : 0.0f;
                    dx = px[u].z - vix; dy = py[u].z - viy;
                    s = fsqrt_fast(dx * dx + dy * dy); sum0 += a[u].z ? s : 0.0f;
                    dx = px[u].w - vix; dy = py[u].w - viy;
                    s = fsqrt_fast(dx * dx + dy * dy); sum1 += a[u].w ? s : 0.0f;
                }
            }
        }
    }

    // ---- block reduction + global accumulate ----
    float bsum = block_sum256(sum0 + sum1, sh);

    if (t == 0) {
        atomicAdd((double*)&g_accum[0], (double)bsum);
        __threadfence();
        unsigned long long prev = atomicAdd(&g_accum[1], 1ULL);
        if (prev == (unsigned long long)(gridDim.x - 1)) {
            // last block: everything (peri partials + block-0 stats) is visible
            double peri_d = __longlong_as_double(
                (long long)atomicAdd(&g_accum[0], 0ULL));
            float peri = (float)peri_d;
            float d1 = g_r - g_gtr;
            float d2 = peri - g_gtperi;
            out[0] = d1 * d1 + d2 * d2;
        }
    }
}

extern "C" void kernel_launch(void* const* d_in, const int* in_sizes, int n_in,
                              void* d_out, int out_size) {
    const float2* verts = (const float2*)d_in[0];
    const float2* gts   = (const float2*)d_in[1];
    const void*   A     = d_in[2];
    float* out = (float*)d_out;

    const int n = in_sizes[0] / 2;   // 8192
    const int m = in_sizes[1] / 2;   // 8192

    void* accum_addr = nullptr;
    cudaGetSymbolAddress(&accum_addr, g_accum);
    cudaMemsetAsync(accum_addr, 0, 2 * sizeof(unsigned long long));

    const size_t smem = (size_t)n * 2 * sizeof(float);   // 64 KB SoA
    cudaFuncSetAttribute(fused_kernel,
                         cudaFuncAttributeMaxDynamicSharedMemorySize,
                         (int)smem + 1024);

    fused_kernel<<<PERI_BLOCKS, PERI_THREADS, smem>>>(verts, gts, A, out, n, m);
}

// round 7
// speedup vs baseline: 2.9277x; 1.6643x over previous
#include <cuda_runtime.h>
#include <math.h>

#define GRID_BLOCKS 888      // ~6 blocks/SM * 148 SMs (no smem; regs-limited)
#define THREADS 256
#define VB 2                 // batches of 4 pairs per thread per iteration

// [0] peri accumulator (double bits), [1] done counter, [2] row work counter
__device__ unsigned long long g_state[3];
__device__ float g_r, g_gtr, g_gtperi;

__device__ __forceinline__ float fsqrt_fast(float x) {
    float r;
    asm("sqrt.approx.f32 %0, %1;" : "=f"(r) : "f"(x));
    return r;
}

// block-wide sum for 256 threads (8 warps)
__device__ __forceinline__ float block_sum256(float v, float* sh) {
    const int t = threadIdx.x;
    for (int o = 16; o > 0; o >>= 1)
        v += __shfl_down_sync(0xffffffffu, v, o);
    if ((t & 31) == 0) sh[t >> 5] = v;
    __syncthreads();
    float r = 0.f;
    if (t < 32) {
        r = (t < 8) ? sh[t] : 0.f;
        for (int o = 4; o > 0; o >>= 1)
            r += __shfl_down_sync(0xffffffffu, r, o);
        if (t == 0) sh[0] = r;
    }
    __syncthreads();
    r = sh[0];
    __syncthreads();
    return r;
}

// ---------------------------------------------------------------------------
// Single fused kernel, NO shared-memory vertex table (verts lives in L1).
//  * Work-stealing row queue: rows handed out ascending (longest first) =>
//    near-perfect load balance regardless of residency/waves.
//  * A read as int4 (int32 layout) or uchar4 (byte layout); verts read as
//    float4 pairs (2 interleaved float2 vertices per load). VB-deep batch.
//  * Block 0 computes r/gtr/gtperi first; last block to finish writes out.
// ---------------------------------------------------------------------------
__global__ void __launch_bounds__(THREADS)
fused_kernel(const float2* __restrict__ verts,
             const float2* __restrict__ gts,
             const void* __restrict__ Araw,
             float* __restrict__ out,
             int n, int m) {
    __shared__ float sh[32];
    __shared__ int s_misc;   // layout flag, then row index
    const int t = threadIdx.x;
    const int B = blockDim.x;

    // ---- layout detect: int32 {0,1} layout has zero bytes at offsets %4!=0 ----
    if (t == 0) s_misc = 0;
    __syncthreads();
    {
        const unsigned char* __restrict__ Ab = (const unsigned char*)Araw;
        int hit = 0;
        for (int k = t; k < 4096; k += B)
            if ((k & 3) != 0 && Ab[k] != 0) hit = 1;
        if (hit) s_misc = 1;
    }
    __syncthreads();
    const bool bytelayout = (s_misc != 0);
    __syncthreads();

    // ---- block 0: stats (r, gtr, gtperi) ----
    if (blockIdx.x == 0) {
        float ax = 0.f, ay = 0.f;
        for (int i = t; i < n; i += B) { float2 v = verts[i]; ax += v.x; ay += v.y; }
        float cx = block_sum256(ax, sh) / (float)n;
        float cy = block_sum256(ay, sh) / (float)n;

        float rs = 0.f;
        for (int i = t; i < n; i += B) {
            float2 v = verts[i];
            float dx = v.x - cx, dy = v.y - cy;
            rs += sqrtf(dx * dx + dy * dy);
        }
        float r = block_sum256(rs, sh) / (float)n;

        float gx = 0.f, gy = 0.f;
        for (int i = t; i < m; i += B) { float2 v = gts[i]; gx += v.x; gy += v.y; }
        float gcx = block_sum256(gx, sh) / (float)m;
        float gcy = block_sum256(gy, sh) / (float)m;

        float gs = 0.f, gp = 0.f;
        for (int i = t; i < m; i += B) {
            float2 v = gts[i];
            float dx = v.x - gcx, dy = v.y - gcy;
            gs += sqrtf(dx * dx + dy * dy);
            float2 w = gts[(i + 1 == m) ? 0 : (i + 1)];
            float ex = v.x - w.x, ey = v.y - w.y;
            gp += sqrtf(ex * ex + ey * ey);
        }
        float gtr    = block_sum256(gs, sh) / (float)m;
        float gtperi = block_sum256(gp, sh);

        if (t == 0) { g_r = r; g_gtr = gtr; g_gtperi = gtperi; }
    }

    // ---- pair-perimeter rows via work-stealing queue ----
    const float4* __restrict__ v4 = (const float4*)verts;  // 2 verts per float4
    float sum0 = 0.f, sum1 = 0.f;

    for (;;) {
        if (t == 0) s_misc = (int)atomicAdd(&g_state[2], 1ULL);
        __syncthreads();
        const int i = s_misc;
        __syncthreads();
        if (i >= n) break;

        const float2 vi = verts[i];
        const float vix = vi.x, viy = vi.y;
        const int jstart  = i + 1;
        const int j4start = (jstart + 3) & ~3;
        const int npro    = j4start - jstart;

        // unaligned head (0..3 elements)
        if (t < npro) {
            int j = jstart + t;
            if (j < n) {
                unsigned int a;
                if (bytelayout) a = ((const unsigned char*)Araw)[(size_t)i * n + j];
                else            a = (unsigned int)((const int*)Araw)[(size_t)i * n + j];
                float2 p = verts[j];
                float dx = p.x - vix, dy = p.y - viy;
                float s = fsqrt_fast(dx * dx + dy * dy);
                sum0 += a ? s : 0.0f;
            }
        }

        if (bytelayout) {
            const unsigned char* __restrict__ row =
                (const unsigned char*)Araw + (size_t)i * (size_t)n;
            for (int jb = j4start + 4 * t; jb < n; jb += VB * 4 * B) {
                uchar4 a[VB]; float4 pa[VB]; float4 pb[VB];
                #pragma unroll
                for (int u = 0; u < VB; u++) {
                    int jj = jb + u * 4 * B;
                    bool ok = jj < n;
                    int js = ok ? jj : 0;
                    a[u] = ok ? *(const uchar4*)(row + js) : make_uchar4(0,0,0,0);
                    pa[u] = v4[js >> 1];            // verts[js], verts[js+1]
                    pb[u] = v4[(js >> 1) + 1];      // verts[js+2], verts[js+3]
                }
                #pragma unroll
                for (int u = 0; u < VB; u++) {
                    float dx, dy, s;
                    dx = pa[u].x - vix; dy = pa[u].y - viy;
                    s = fsqrt_fast(dx * dx + dy * dy); sum0 += a[u].x ? s : 0.0f;
                    dx = pa[u].z - vix; dy = pa[u].w - viy;
                    s = fsqrt_fast(dx * dx + dy * dy); sum1 += a[u].y ? s : 0.0f;
                    dx = pb[u].x - vix; dy = pb[u].y - viy;
                    s = fsqrt_fast(dx * dx + dy * dy); sum0 += a[u].z ? s : 0.0f;
                    dx = pb[u].z - vix; dy = pb[u].w - viy;
                    s = fsqrt_fast(dx * dx + dy * dy); sum1 += a[u].w ? s : 0.0f;
                }
            }
        } else {
            const int* __restrict__ row =
                (const int*)Araw + (size_t)i * (size_t)n;
            for (int jb = j4start + 4 * t; jb < n; jb += VB * 4 * B) {
                int4 a[VB]; float4 pa[VB]; float4 pb[VB];
                #pragma unroll
                for (int u = 0; u < VB; u++) {
                    int jj = jb + u * 4 * B;
                    bool ok = jj < n;
                    int js = ok ? jj : 0;
                    a[u] = ok ? *(const int4*)(row + js) : make_int4(0,0,0,0);
                    pa[u] = v4[js >> 1];
                    pb[u] = v4[(js >> 1) + 1];
                }
                #pragma unroll
                for (int u = 0; u < VB; u++) {
                    float dx, dy, s;
                    dx = pa[u].x - vix; dy = pa[u].y - viy;
                    s = fsqrt_fast(dx * dx + dy * dy); sum0 += a[u].x ? s : 0.0f;
                    dx = pa[u].z - vix; dy = pa[u].w - viy;
                    s = fsqrt_fast(dx * dx + dy * dy); sum1 += a[u].y ? s : 0.0f;
                    dx = pb[u].x - vix; dy = pb[u].y - viy;
                    s = fsqrt_fast(dx * dx + dy * dy); sum0 += a[u].z ? s : 0.0f;
                    dx = pb[u].z - vix; dy = pb[u].w - viy;
                    s = fsqrt_fast(dx * dx + dy * dy); sum1 += a[u].w ? s : 0.0f;
                }
            }
        }
    }

    // ---- block reduction + global accumulate + last-block finalize ----
    float bsum = block_sum256(sum0 + sum1, sh);

    if (t == 0) {
        atomicAdd((double*)&g_state[0], (double)bsum);
        __threadfence();
        unsigned long long prev = atomicAdd(&g_state[1], 1ULL);
        if (prev == (unsigned long long)(gridDim.x - 1)) {
            double peri_d = __longlong_as_double(
                (long long)atomicAdd(&g_state[0], 0ULL));
            float peri = (float)peri_d;
            float d1 = g_r - g_gtr;
            float d2 = peri - g_gtperi;
            out[0] = d1 * d1 + d2 * d2;
        }
    }
}

extern "C" void kernel_launch(void* const* d_in, const int* in_sizes, int n_in,
                              void* d_out, int out_size) {
    const float2* verts = (const float2*)d_in[0];
    const float2* gts   = (const float2*)d_in[1];
    const void*   A     = d_in[2];
    float* out = (float*)d_out;

    const int n = in_sizes[0] / 2;   // 8192
    const int m = in_sizes[1] / 2;   // 8192

    void* state_addr = nullptr;
    cudaGetSymbolAddress(&state_addr, g_state);
    cudaMemsetAsync(state_addr, 0, 3 * sizeof(unsigned long long));

    fused_kernel<<<GRID_BLOCKS, THREADS>>>(verts, gts, A, out, n, m);
}

// round 8
// speedup vs baseline: 3.4285x; 1.1711x over previous
#include <cuda_runtime.h>
#include <math.h>

#define GRID_BLOCKS 888
#define THREADS 256
#define VB 2                 // batches of 4 pairs per row per iteration

// [0] peri accumulator (double bits), [1] done counter, [2] row-pair ticket
__device__ unsigned long long g_state[3];
__device__ float g_r, g_gtr, g_gtperi;

__device__ __forceinline__ float fsqrt_fast(float x) {
    float r;
    asm("sqrt.approx.f32 %0, %1;" : "=f"(r) : "f"(x));
    return r;
}

// block-wide sum for 256 threads (8 warps)
__device__ __forceinline__ float block_sum256(float v, float* sh) {
    const int t = threadIdx.x;
    for (int o = 16; o > 0; o >>= 1)
        v += __shfl_down_sync(0xffffffffu, v, o);
    if ((t & 31) == 0) sh[t >> 5] = v;
    __syncthreads();
    float r = 0.f;
    if (t < 32) {
        r = (t < 8) ? sh[t] : 0.f;
        for (int o = 4; o > 0; o >>= 1)
            r += __shfl_down_sync(0xffffffffu, r, o);
        if (t == 0) sh[0] = r;
    }
    __syncthreads();
    r = sh[0];
    __syncthreads();
    return r;
}

// ---------------------------------------------------------------------------
// Fused kernel. Work queue hands out ROW PAIRS (i, i+1): both rows share the
// same vertex loads (halved vertex L1 traffic) and loop overhead. Main loop
// is fully unchecked (n % 4 == 0, 4-aligned tiles); remainder loop aligned.
// ---------------------------------------------------------------------------
__global__ void __launch_bounds__(THREADS)
fused_kernel(const float2* __restrict__ verts,
             const float2* __restrict__ gts,
             const void* __restrict__ Araw,
             float* __restrict__ out,
             int n, int m) {
    __shared__ float sh[32];
    __shared__ int s_misc;
    const int t = threadIdx.x;
    const int B = blockDim.x;

    // ---- layout detect: int32 {0,1} layout has zero bytes at offsets %4!=0 ----
    if (t == 0) s_misc = 0;
    __syncthreads();
    {
        const unsigned char* __restrict__ Ab = (const unsigned char*)Araw;
        int hit = 0;
        for (int k = t; k < 4096; k += B)
            if ((k & 3) != 0 && Ab[k] != 0) hit = 1;
        if (hit) s_misc = 1;
    }
    __syncthreads();
    const bool bytelayout = (s_misc != 0);
    __syncthreads();

    // ---- block 0: stats (r, gtr, gtperi) ----
    if (blockIdx.x == 0) {
        float ax = 0.f, ay = 0.f;
        for (int i = t; i < n; i += B) { float2 v = verts[i]; ax += v.x; ay += v.y; }
        float cx = block_sum256(ax, sh) / (float)n;
        float cy = block_sum256(ay, sh) / (float)n;

        float rs = 0.f;
        for (int i = t; i < n; i += B) {
            float2 v = verts[i];
            float dx = v.x - cx, dy = v.y - cy;
            rs += sqrtf(dx * dx + dy * dy);
        }
        float r = block_sum256(rs, sh) / (float)n;

        float gx = 0.f, gy = 0.f;
        for (int i = t; i < m; i += B) { float2 v = gts[i]; gx += v.x; gy += v.y; }
        float gcx = block_sum256(gx, sh) / (float)m;
        float gcy = block_sum256(gy, sh) / (float)m;

        float gs = 0.f, gp = 0.f;
        for (int i = t; i < m; i += B) {
            float2 v = gts[i];
            float dx = v.x - gcx, dy = v.y - gcy;
            gs += sqrtf(dx * dx + dy * dy);
            float2 w = gts[(i + 1 == m) ? 0 : (i + 1)];
            float ex = v.x - w.x, ey = v.y - w.y;
            gp += sqrtf(ex * ex + ey * ey);
        }
        float gtr    = block_sum256(gs, sh) / (float)m;
        float gtperi = block_sum256(gp, sh);

        if (t == 0) { g_r = r; g_gtr = gtr; g_gtperi = gtperi; }
    }

    // ---- pair-perimeter: row pairs via work-stealing queue ----
    const float4* __restrict__ v4 = (const float4*)verts;  // 2 verts per float4
    float s00 = 0.f, s01 = 0.f, s10 = 0.f, s11 = 0.f;

    for (;;) {
        if (t == 0)
            s_misc = 2 * (int)atomicAdd(&g_state[2], 1ULL);
        __syncthreads();
        const int i0 = s_misc;
        __syncthreads();
        if (i0 >= n) break;
        const int i1 = i0 + 1;            // n is even => i1 < n always here

        const float2 va = verts[i0];
        const float2 vb = verts[i1];
        const float vix0 = va.x, viy0 = va.y;
        const float vix1 = vb.x, viy1 = vb.y;

        const size_t base0 = (size_t)i0 * (size_t)n;
        const size_t base1 = (size_t)i1 * (size_t)n;

        // pair (i0, i1) belongs only to row i0
        if (t == 0) {
            unsigned int a;
            if (bytelayout) a = ((const unsigned char*)Araw)[base0 + i1];
            else            a = (unsigned int)((const int*)Araw)[base0 + i1];
            float dx = vix1 - vix0, dy = viy1 - viy0;
            float s = fsqrt_fast(dx * dx + dy * dy);
            s00 += a ? s : 0.0f;
        }

        const int jstart = i1 + 1;                 // joint start for both rows
        const int j4start = (jstart + 3) & ~3;
        const int npro = j4start - jstart;

        if (t < npro) {
            int j = jstart + t;
            if (j < n) {
                unsigned int a0, a1;
                if (bytelayout) {
                    a0 = ((const unsigned char*)Araw)[base0 + j];
                    a1 = ((const unsigned char*)Araw)[base1 + j];
                } else {
                    a0 = (unsigned int)((const int*)Araw)[base0 + j];
                    a1 = (unsigned int)((const int*)Araw)[base1 + j];
                }
                float2 p = verts[j];
                float dx0 = p.x - vix0, dy0 = p.y - viy0;
                float dx1 = p.x - vix1, dy1 = p.y - viy1;
                float d0 = fsqrt_fast(dx0 * dx0 + dy0 * dy0);
                float d1 = fsqrt_fast(dx1 * dx1 + dy1 * dy1);
                s00 += a0 ? d0 : 0.0f;
                s10 += a1 ? d1 : 0.0f;
            }
        }

        if (bytelayout) {
            const unsigned char* __restrict__ row0 = (const unsigned char*)Araw + base0;
            const unsigned char* __restrict__ row1 = (const unsigned char*)Araw + base1;
            int jb = j4start + 4 * t;
            // main loop: 2 batches, no bounds checks (n % 4 == 0, tiles aligned)
            for (; jb + 4 * B < n; jb += VB * 4 * B) {
                uchar4 a0[VB], a1[VB]; float4 pa[VB], pb[VB];
                #pragma unroll
                for (int u = 0; u < VB; u++) {
                    int js = jb + u * 4 * B;
                    a0[u] = *(const uchar4*)(row0 + js);
                    a1[u] = *(const uchar4*)(row1 + js);
                    pa[u] = v4[js >> 1];
                    pb[u] = v4[(js >> 1) + 1];
                }
                #pragma unroll
                for (int u = 0; u < VB; u++) {
                    float dx, dy, s;
                    dx = pa[u].x - vix0; dy = pa[u].y - viy0;
                    s = fsqrt_fast(dx*dx + dy*dy); s00 += a0[u].x ? s : 0.0f;
                    dx = pa[u].x - vix1; dy = pa[u].y - viy1;
                    s = fsqrt_fast(dx*dx + dy*dy); s10 += a1[u].x ? s : 0.0f;
                    dx = pa[u].z - vix0; dy = pa[u].w - viy0;
                    s = fsqrt_fast(dx*dx + dy*dy); s01 += a0[u].y ? s : 0.0f;
                    dx = pa[u].z - vix1; dy = pa[u].w - viy1;
                    s = fsqrt_fast(dx*dx + dy*dy); s11 += a1[u].y ? s : 0.0f;
                    dx = pb[u].x - vix0; dy = pb[u].y - viy0;
                    s = fsqrt_fast(dx*dx + dy*dy); s00 += a0[u].z ? s : 0.0f;
                    dx = pb[u].x - vix1; dy = pb[u].y - viy1;
                    s = fsqrt_fast(dx*dx + dy*dy); s10 += a1[u].z ? s : 0.0f;
                    dx = pb[u].z - vix0; dy = pb[u].w - viy0;
                    s = fsqrt_fast(dx*dx + dy*dy); s01 += a0[u].w ? s : 0.0f;
                    dx = pb[u].z - vix1; dy = pb[u].w - viy1;
                    s = fsqrt_fast(dx*dx + dy*dy); s11 += a1[u].w ? s : 0.0f;
                }
            }
            // remainder: single batch, still no element checks (aligned)
            for (; jb < n; jb += 4 * B) {
                uchar4 a0 = *(const uchar4*)(row0 + jb);
                uchar4 a1 = *(const uchar4*)(row1 + jb);
                float4 pa = v4[jb >> 1];
                float4 pb = v4[(jb >> 1) + 1];
                float dx, dy, s;
                dx = pa.x - vix0; dy = pa.y - viy0;
                s = fsqrt_fast(dx*dx + dy*dy); s00 += a0.x ? s : 0.0f;
                dx = pa.x - vix1; dy = pa.y - viy1;
                s = fsqrt_fast(dx*dx + dy*dy); s10 += a1.x ? s : 0.0f;
                dx = pa.z - vix0; dy = pa.w - viy0;
                s = fsqrt_fast(dx*dx + dy*dy); s01 += a0.y ? s : 0.0f;
                dx = pa.z - vix1; dy = pa.w - viy1;
                s = fsqrt_fast(dx*dx + dy*dy); s11 += a1.y ? s : 0.0f;
                dx = pb.x - vix0; dy = pb.y - viy0;
                s = fsqrt_fast(dx*dx + dy*dy); s00 += a0.z ? s : 0.0f;
                dx = pb.x - vix1; dy = pb.y - viy1;
                s = fsqrt_fast(dx*dx + dy*dy); s10 += a1.z ? s : 0.0f;
                dx = pb.z - vix0; dy = pb.w - viy0;
                s = fsqrt_fast(dx*dx + dy*dy); s01 += a0.w ? s : 0.0f;
                dx = pb.z - vix1; dy = pb.w - viy1;
                s = fsqrt_fast(dx*dx + dy*dy); s11 += a1.w ? s : 0.0f;
            }
        } else {
            const int* __restrict__ row0 = (const int*)Araw + base0;
            const int* __restrict__ row1 = (const int*)Araw + base1;
            int jb = j4start + 4 * t;
            for (; jb + 4 * B < n; jb += VB * 4 * B) {
                int4 a0[VB], a1[VB]; float4 pa[VB], pb[VB];
                #pragma unroll
                for (int u = 0; u < VB; u++) {
                    int js = jb + u * 4 * B;
                    a0[u] = *(const int4*)(row0 + js);
                    a1[u] = *(const int4*)(row1 + js);
                    pa[u] = v4[js >> 1];
                    pb[u] = v4[(js >> 1) + 1];
                }
                #pragma unroll
                for (int u = 0; u < VB; u++) {
                    float dx, dy, s;
                    dx = pa[u].x - vix0; dy = pa[u].y - viy0;
                    s = fsqrt_fast(dx*dx + dy*dy); s00 += a0[u].x ? s : 0.0f;
                    dx = pa[u].x - vix1; dy = pa[u].y - viy1;
                    s = fsqrt_fast(dx*dx + dy*dy); s10 += a1[u].x ? s : 0.0f;
                    dx = pa[u].z - vix0; dy = pa[u].w - viy0;
                    s = fsqrt_fast(dx*dx + dy*dy); s01 += a0[u].y ? s : 0.0f;
                    dx = pa[u].z - vix1; dy = pa[u].w - viy1;
                    s = fsqrt_fast(dx*dx + dy*dy); s11 += a1[u].y ? s : 0.0f;
                    dx = pb[u].x - vix0; dy = pb[u].y - viy0;
                    s = fsqrt_fast(dx*dx + dy*dy); s00 += a0[u].z ? s : 0.0f;
                    dx = pb[u].x - vix1; dy = pb[u].y - viy1;
                    s = fsqrt_fast(dx*dx + dy*dy); s10 += a1[u].z ? s : 0.0f;
                    dx = pb[u].z - vix0; dy = pb[u].w - viy0;
                    s = fsqrt_fast(dx*dx + dy*dy); s01 += a0[u].w ? s : 0.0f;
                    dx = pb[u].z - vix1; dy = pb[u].w - viy1;
                    s = fsqrt_fast(dx*dx + dy*dy); s11 += a1[u].w ? s : 0.0f;
                }
            }
            for (; jb < n; jb += 4 * B) {
                int4 a0 = *(const int4*)(row0 + jb);
                int4 a1 = *(const int4*)(row1 + jb);
                float4 pa = v4[jb >> 1];
                float4 pb = v4[(jb >> 1) + 1];
                float dx, dy, s;
                dx = pa.x - vix0; dy = pa.y - viy0;
                s = fsqrt_fast(dx*dx + dy*dy); s00 += a0.x ? s : 0.0f;
                dx = pa.x - vix1; dy = pa.y - viy1;
                s = fsqrt_fast(dx*dx + dy*dy); s10 += a1.x ? s : 0.0f;
                dx = pa.z - vix0; dy = pa.w - viy0;
                s = fsqrt_fast(dx*dx + dy*dy); s01 += a0.y ? s : 0.0f;
                dx = pa.z - vix1; dy = pa.w - viy1;
                s = fsqrt_fast(dx*dx + dy*dy); s11 += a1.y ? s : 0.0f;
                dx = pb.x - vix0; dy = pb.y - viy0;
                s = fsqrt_fast(dx*dx + dy*dy); s00 += a0.z ? s : 0.0f;
                dx = pb.x - vix1; dy = pb.y - viy1;
                s = fsqrt_fast(dx*dx + dy*dy); s10 += a1.z ? s : 0.0f;
                dx = pb.z - vix0; dy = pb.w - viy0;
                s = fsqrt_fast(dx*dx + dy*dy); s01 += a0.w ? s : 0.0f;
                dx = pb.z - vix1; dy = pb.w - viy1;
                s = fsqrt_fast(dx*dx + dy*dy); s11 += a1.w ? s : 0.0f;
            }
        }
    }

    // ---- block reduction + global accumulate + last-block finalize ----
    float bsum = block_sum256((s00 + s01) + (s10 + s11), sh);

    if (t == 0) {
        atomicAdd((double*)&g_state[0], (double)bsum);
        __threadfence();
        unsigned long long prev = atomicAdd(&g_state[1], 1ULL);
        if (prev == (unsigned long long)(gridDim.x - 1)) {
            double peri_d = __longlong_as_double(
                (long long)atomicAdd(&g_state[0], 0ULL));
            float peri = (float)peri_d;
            float d1 = g_r - g_gtr;
            float d2 = peri - g_gtperi;
            out[0] = d1 * d1 + d2 * d2;
        }
    }
}

extern "C" void kernel_launch(void* const* d_in, const int* in_sizes, int n_in,
                              void* d_out, int out_size) {
    const float2* verts = (const float2*)d_in[0];
    const float2* gts   = (const float2*)d_in[1];
    const void*   A     = d_in[2];
    float* out = (float*)d_out;

    const int n = in_sizes[0] / 2;   // 8192
    const int m = in_sizes[1] / 2;   // 8192

    void* state_addr = nullptr;
    cudaGetSymbolAddress(&state_addr, g_state);
    cudaMemsetAsync(state_addr, 0, 3 * sizeof(unsigned long long));

    fused_kernel<<<GRID_BLOCKS, THREADS>>>(verts, gts, A, out, n, m);
}